// round 7
// baseline (speedup 1.0000x reference)
#include <cuda_runtime.h>
#include <cstdint>

#define BATCH 8
#define NA 3
#define NC 80
#define HH 160
#define WW 160
#define HW 25600      // HH*WW
#define NPB 76800     // NA*HW candidates per batch
#define TOPKK 100
#define MTARGET 768   // E1 target size per batch (phase C covers any shortfall exactly)
#define NBIN 4096
#define GRID 512      // co-resident: needs only 128 SMs at 4 blocks/SM (B200 has 148)
#define NTILE 600     // 75 tiles per batch
#define CANDCAP 192

typedef unsigned long long u64;
typedef unsigned int u32;
typedef unsigned char u8;

// ---------------- static device scratch (zero-init at load; phase D re-zeros per batch) ---------
__device__ float g_ub[BATCH * NPB];
__device__ u64  g_keys[BATCH * NPB];
__device__ u8   g_cls[BATCH * NPB];
__device__ u32  g_ubhist[BATCH * NBIN];
__device__ u32  g_schist[BATCH * NBIN];
__device__ int  g_cnt1[BATCH], g_cnt2[BATCH];
__device__ u32  g_T1[BATCH], g_T2[BATCH];
__device__ int  g_tick1[BATCH], g_tick2[BATCH], g_tick3[BATCH];
__device__ int  g_flag1[BATCH], g_flag2[BATCH];

__device__ __forceinline__ float fsig(float x) { return 1.0f / (1.0f + __expf(-x)); }

// warp-collective: max+argmax over 80 class logits -> exact score key; writes class byte
__device__ __forceinline__ u64 evalCand(const float* __restrict__ cls, int b, int idx, int lane) {
    int a = idx / HW;
    int pix = idx - a * HW;
    const float* cp = cls + (size_t)(b * NA + a) * NC * HW + pix;
    float m = cp[(size_t)lane * HW];
    int c = lane;
    float v = cp[(size_t)(lane + 32) * HW];
    if (v > m) { m = v; c = lane + 32; }
    if (lane < 16) {
        float w = cp[(size_t)(lane + 64) * HW];
        if (w > m) { m = w; c = lane + 64; }
    }
#pragma unroll
    for (int off = 16; off; off >>= 1) {
        float om = __shfl_xor_sync(0xffffffffu, m, off);
        int   oc = __shfl_xor_sync(0xffffffffu, c, off);
        if (om > m || (om == m && oc < c)) { m = om; c = oc; }
    }
    float ub = g_ub[b * NPB + idx];
    // IEEE division with denom >= 1  =>  score <= ub bitwise (pruning invariant)
    float score = __fdiv_rn(ub, 1.0f + __expf(-m));
    if (lane == 0) g_cls[b * NPB + idx] = (u8)c;
    return ((u64)__float_as_uint(score) << 17) | (u32)(NPB - 1 - idx);
}

// 256-thread top-K boundary pick over smem hist h with bpt bins/thread (bpt*256 bins).
// Outputs (via shared): *sd = boundary bin, *sLab = count strictly above, *sC = count >= bin.
__device__ __forceinline__ void pickTop(u32* h, int bpt, u32* scan, int need,
                                        int* sd, int* sLab, int* sC) {
    int t = threadIdx.x;
    int base = t * bpt;
    u32 ssum = 0;
    for (int q = 0; q < bpt; q++) ssum += h[base + q];
    scan[t] = ssum;
    __syncthreads();
    for (int d = 1; d < 256; d <<= 1) {          // inclusive suffix scan
        u32 v = (t + d < 256) ? scan[t + d] : 0u;
        __syncthreads();
        scan[t] += v;
        __syncthreads();
    }
    u32 above = (t < 255) ? scan[t + 1] : 0u;
    if ((int)scan[t] >= need && (int)above < need) {   // exactly one thread
        u32 cum = above;
        int d;
        for (d = base + bpt - 1;; d--) {
            if ((int)(cum + h[d]) >= need) break;
            cum += h[d];
        }
        *sd = d; *sLab = (int)cum; *sC = (int)(cum + h[d]);
    }
    __syncthreads();
}

// load global hist -> pick boundary -> publish threshold + release flag (single-thread ordering)
__device__ void selectBinFlag(const u32* __restrict__ gh, int K, u32* outT, int* flag,
                              u32* h, u32* scan, int* sd, int* sLab, int* sC) {
    for (int j = threadIdx.x; j < NBIN; j += 256) h[j] = gh[j];
    __syncthreads();
    pickTop(h, 16, scan, K, sd, sLab, sC);
    if (threadIdx.x == 0) {
        *outT = (u32)*sd;
        __threadfence();
        *(volatile int*)flag = 1;
    }
    __syncthreads();
}

__device__ __forceinline__ void spinFlag(int* f) {
    if (threadIdx.x == 0) {
        volatile int* vf = f;
        while (*vf == 0) __nanosleep(64);
    }
    __syncthreads();
    __threadfence();
}

// =================================== the whole pipeline ===================================
__global__ void __launch_bounds__(256, 4) fusedK(const float* __restrict__ obj,
                                                 const float* __restrict__ qual,
                                                 const float* __restrict__ cls,
                                                 const float* __restrict__ box,
                                                 const float* __restrict__ anch,
                                                 float* __restrict__ out) {
    __shared__ u32 shh[NBIN];        // 16 KB
    __shared__ int sbuf[1024];       // 4 KB  (phase D: aliased as 1024-bin sub-hist)
    __shared__ u32 scan256[256];     // 1 KB
    __shared__ u64 cand[CANDCAP];    // 1.5 KB
    __shared__ int s_n, s_pos, s_last, s_d, s_L, s_C, s_cnt;

    int tid = threadIdx.x, lane = tid & 31, warp = tid >> 5;
    int tiles[2];
    int nt = 0;
    tiles[nt++] = blockIdx.x;
    if (blockIdx.x + GRID < NTILE) tiles[nt++] = blockIdx.x + GRID;

    // ---------------- Phase A: ub + hist; last tile of batch picks T1 ----------------
    for (int it = 0; it < nt; it++) {
        int t = tiles[it], b = t / 75, ti = t - b * 75;
        int g0 = b * NPB + ti * 1024 + tid * 4;
        for (int j = tid; j < NBIN; j += 256) shh[j] = 0;
        __syncthreads();

        float4 o4 = *reinterpret_cast<const float4*>(obj + g0);
        float4 q4 = *reinterpret_cast<const float4*>(qual + g0);
        float u0 = 1.0f / ((1.0f + __expf(-o4.x)) * (1.0f + __expf(-q4.x)));
        float u1 = 1.0f / ((1.0f + __expf(-o4.y)) * (1.0f + __expf(-q4.y)));
        float u2 = 1.0f / ((1.0f + __expf(-o4.z)) * (1.0f + __expf(-q4.z)));
        float u3 = 1.0f / ((1.0f + __expf(-o4.w)) * (1.0f + __expf(-q4.w)));
        *reinterpret_cast<float4*>(g_ub + g0) = make_float4(u0, u1, u2, u3);
        atomicAdd(&shh[__float_as_uint(u0) >> 18], 1u);
        atomicAdd(&shh[__float_as_uint(u1) >> 18], 1u);
        atomicAdd(&shh[__float_as_uint(u2) >> 18], 1u);
        atomicAdd(&shh[__float_as_uint(u3) >> 18], 1u);
        __syncthreads();

        u32* gh = g_ubhist + b * NBIN;
        for (int j = tid; j < NBIN; j += 256) {
            u32 v = shh[j];
            if (v) atomicAdd(&gh[j], v);
        }
        __syncthreads();
        if (tid == 0) {
            __threadfence();
            s_last = (atomicAdd(&g_tick1[b], 1) == 74) ? 1 : 0;
        }
        __syncthreads();
        if (s_last)
            selectBinFlag(gh, MTARGET, &g_T1[b], &g_flag1[b], shh, scan256, &s_d, &s_L, &s_C);
        __syncthreads();
    }

    // ---------------- Phase B: E1 collect+eval; last tile picks T2 ----------------
    for (int it = 0; it < nt; it++) {
        int t = tiles[it], b = t / 75, ti = t - b * 75;
        int i0 = ti * 1024 + tid * 4;
        spinFlag(&g_flag1[b]);
        u32 T1 = g_T1[b];
        if (tid == 0) s_n = 0;
        __syncthreads();

        float4 u4 = *reinterpret_cast<const float4*>(g_ub + b * NPB + i0);
        float us[4] = {u4.x, u4.y, u4.z, u4.w};
#pragma unroll
        for (int j = 0; j < 4; j++) {
            if ((__float_as_uint(us[j]) >> 18) >= T1) {
                int p = atomicAdd(&s_n, 1);
                sbuf[p] = i0 + j;
            }
        }
        __syncthreads();
        if (tid == 0) s_pos = s_n ? atomicAdd(&g_cnt1[b], s_n) : 0;
        __syncthreads();

        int n = s_n, pos = s_pos;
        for (int j = warp; j < n; j += 8) {
            u64 key = evalCand(cls, b, sbuf[j], lane);
            if (lane == 0) {
                g_keys[(size_t)b * NPB + pos + j] = key;
                atomicAdd(&g_schist[b * NBIN + (u32)(key >> 35)], 1u);
            }
        }
        __syncthreads();
        if (tid == 0) {
            __threadfence();
            s_last = (atomicAdd(&g_tick2[b], 1) == 74) ? 1 : 0;
        }
        __syncthreads();
        if (s_last)
            selectBinFlag(g_schist + b * NBIN, TOPKK, &g_T2[b], &g_flag2[b],
                          shh, scan256, &s_d, &s_L, &s_C);
        __syncthreads();
    }

    // ---------------- Phase C: E2 (ub bin in [T2, T1)) collect+eval ----------------
    for (int it = 0; it < nt; it++) {
        int t = tiles[it], b = t / 75, ti = t - b * 75;
        int i0 = ti * 1024 + tid * 4;
        spinFlag(&g_flag2[b]);
        u32 T1 = g_T1[b], T2 = g_T2[b];
        if (T2 < T1) {
            if (tid == 0) s_n = 0;
            __syncthreads();
            float4 u4 = *reinterpret_cast<const float4*>(g_ub + b * NPB + i0);
            float us[4] = {u4.x, u4.y, u4.z, u4.w};
#pragma unroll
            for (int j = 0; j < 4; j++) {
                u32 bin = __float_as_uint(us[j]) >> 18;
                if (bin >= T2 && bin < T1) {
                    int p = atomicAdd(&s_n, 1);
                    sbuf[p] = i0 + j;
                }
            }
            __syncthreads();
            if (tid == 0) s_pos = s_n ? (g_cnt1[b] + atomicAdd(&g_cnt2[b], s_n)) : 0;
            __syncthreads();
            int n = s_n, pos = s_pos;
            for (int j = warp; j < n; j += 8) {
                u64 key = evalCand(cls, b, sbuf[j], lane);
                if (lane == 0) g_keys[(size_t)b * NPB + pos + j] = key;
            }
            __syncthreads();
        }
        if (tid == 0) {
            __threadfence();
            atomicAdd(&g_tick3[b], 1);
        }
        __syncthreads();
    }

    // ---------------- Phase D (blocks 0..7): exact top-100 over all M keys ----------------
    if (blockIdx.x < BATCH) {
        int b = blockIdx.x;
        if (tid == 0) {
            volatile int* vt = &g_tick3[b];
            while (*vt < 75) __nanosleep(64);
        }
        __syncthreads();
        __threadfence();

        int M = g_cnt1[b] + g_cnt2[b];
        const u64* keys = g_keys + (size_t)b * NPB;

        // level 0: 4096-bin histogram of key>>35 (score bits >> 18, values < 4096)
        for (int j = tid; j < NBIN; j += 256) shh[j] = 0;
        __syncthreads();
        for (int j = tid; j < M; j += 256)
            atomicAdd(&shh[(u32)(keys[j] >> 35)], 1u);
        __syncthreads();
        pickTop(shh, 16, scan256, TOPKK, &s_d, &s_L, &s_C);
        u64 P = (u64)(u32)s_d;
        int s = 35, L = s_L, C = s_C;
        __syncthreads();

        // 10-bit refinement levels (25, 15, 5); invariant L < 100 at every level.
        // At s=5 a bucket holds <=32 keys (idx low bits), so C <= 131 is guaranteed.
        u32* subh = reinterpret_cast<u32*>(sbuf);
        while (C > CANDCAP && s > 5) {
            int s2 = s - 10;
            for (int j = tid; j < 1024; j += 256) subh[j] = 0;
            __syncthreads();
            for (int j = tid; j < M; j += 256) {
                u64 k = keys[j];
                if ((k >> s) == P) atomicAdd(&subh[(u32)(k >> s2) & 1023], 1u);
            }
            __syncthreads();
            pickTop(subh, 4, scan256, TOPKK - L, &s_d, &s_L, &s_C);
            int Lsub = s_L, Csub = s_C;
            __syncthreads();
            P = (P << 10) | (u32)s_d;
            s = s2;
            C = L + Csub;
            L = L + Lsub;
        }

        // collect candidates >= threshold (C <= CANDCAP guaranteed)
        if (tid == 0) s_cnt = 0;
        __syncthreads();
        for (int j = tid; j < M; j += 256) {
            u64 k = keys[j];
            if ((k >> s) >= P) {
                int pos = atomicAdd(&s_cnt, 1);
                if (pos < CANDCAP) cand[pos] = k;
            }
        }
        __syncthreads();
        int Cn = min(s_cnt, CANDCAP);

        // rank by counting (keys distinct -> exact permutation), decode inline
        for (int i = tid; i < Cn; i += 256) {
            u64 k = cand[i];
            int r = 0;
            for (int j = 0; j < Cn; j++) r += (cand[j] > k);
            if (r < TOPKK) {
                u32 sb = (u32)(k >> 17);
                int idx = NPB - 1 - (int)(k & 0x1FFFFu);
                int a = idx / HW;
                int pix = idx - a * HW;
                int y = pix / WW;
                int x = pix - y * WW;
                int c = (int)g_cls[b * NPB + idx];
                const float* bp = box + (size_t)(b * NA + a) * 4 * HW + pix;
                float tx = bp[0];
                float ty = bp[(size_t)HW];
                float tw = bp[2 * (size_t)HW];
                float th = bp[3 * (size_t)HW];
                float aw = anch[a * 2 + 0];
                float ah = anch[a * 2 + 1];
                float cx = (fsig(tx) + (float)x) / (float)WW;
                float cy = (fsig(ty) + (float)y) / (float)HH;
                // faithful softplus: relu(x) + log1p(exp(-|x|))
                float spw = fmaxf(tw, 0.0f) + log1pf(__expf(-fabsf(tw)));
                float sph = fmaxf(th, 0.0f) + log1pf(__expf(-fabsf(th)));
                float* o = out + ((size_t)b * TOPKK + r) * 6;
                o[0] = __uint_as_float(sb);
                o[1] = (float)c;
                o[2] = cx;
                o[3] = cy;
                o[4] = aw * spw;
                o[5] = ah * sph;
            }
        }

        // reset batch-b scratch for the next replay
        __syncthreads();
        for (int j = tid; j < NBIN; j += 256) {
            g_ubhist[b * NBIN + j] = 0;
            g_schist[b * NBIN + j] = 0;
        }
        if (tid == 0) {
            g_cnt1[b] = 0; g_cnt2[b] = 0;
            g_tick1[b] = 0; g_tick2[b] = 0; g_tick3[b] = 0;
            g_flag1[b] = 0; g_flag2[b] = 0;
        }
    }
}

// ---------------- launch ----------------
extern "C" void kernel_launch(void* const* d_in, const int* in_sizes, int n_in,
                              void* d_out, int out_size) {
    const float* box  = (const float*)d_in[0];
    const float* obj  = (const float*)d_in[1];
    const float* qual = (const float*)d_in[2];
    const float* cls  = (const float*)d_in[3];
    const float* anch = (const float*)d_in[4];
    int seen = 0;
    for (int i = 0; i < n_in; i++) {
        int s = in_sizes[i];
        if (s == BATCH * NA * 4 * HW) box = (const float*)d_in[i];
        else if (s == BATCH * NA * NC * HW) cls = (const float*)d_in[i];
        else if (s == NA * 2) anch = (const float*)d_in[i];
        else if (s == BATCH * NA * HW) {
            if (seen == 0) obj = (const float*)d_in[i];
            else qual = (const float*)d_in[i];
            seen++;
        }
    }
    float* out = (float*)d_out;

    fusedK<<<GRID, 256>>>(obj, qual, cls, box, anch, out);
}

// round 8
// speedup vs baseline: 1.1869x; 1.1869x over previous
#include <cuda_runtime.h>
#include <cstdint>

#define BATCH 8
#define NA 3
#define NC 80
#define HH 160
#define WW 160
#define HW 25600      // HH*WW
#define NPB 76800     // NA*HW candidates per batch
#define TOPKK 100
#define MTARGET 768   // E1 target size per batch (E2 covers any shortfall exactly)
#define NBIN 4096
#define CANDCAP 192

typedef unsigned long long u64;
typedef unsigned int u32;
typedef unsigned char u8;

// ---------------- static device scratch (zero-init at load; finalize re-zeros per batch) --------
__device__ float g_ub[BATCH * NPB];
__device__ u64  g_keys[BATCH * NPB];
__device__ u8   g_cls[BATCH * NPB];
__device__ u32  g_ubhist[BATCH * NBIN];
__device__ u32  g_schist[BATCH * NBIN];
__device__ int  g_cnt1[BATCH], g_cnt2[BATCH];
__device__ u32  g_T1[BATCH], g_T2[BATCH];
__device__ int  g_tick1[BATCH], g_tick2[BATCH], g_tick3[BATCH];

__device__ __forceinline__ float fsig(float x) { return 1.0f / (1.0f + __expf(-x)); }

// warp-collective: max+argmax over 80 class logits -> exact score key; writes class byte
__device__ __forceinline__ u64 evalCand(const float* __restrict__ cls, int b, int idx, int lane) {
    int a = idx / HW;
    int pix = idx - a * HW;
    const float* cp = cls + (size_t)(b * NA + a) * NC * HW + pix;
    float m = cp[(size_t)lane * HW];
    int c = lane;
    float v = cp[(size_t)(lane + 32) * HW];
    if (v > m) { m = v; c = lane + 32; }
    if (lane < 16) {
        float w = cp[(size_t)(lane + 64) * HW];
        if (w > m) { m = w; c = lane + 64; }
    }
#pragma unroll
    for (int off = 16; off; off >>= 1) {
        float om = __shfl_xor_sync(0xffffffffu, m, off);
        int   oc = __shfl_xor_sync(0xffffffffu, c, off);
        if (om > m || (om == m && oc < c)) { m = om; c = oc; }
    }
    float ub = g_ub[b * NPB + idx];
    // IEEE division with denom >= 1  =>  score <= ub bitwise (pruning invariant)
    float score = __fdiv_rn(ub, 1.0f + __expf(-m));
    if (lane == 0) g_cls[b * NPB + idx] = (u8)c;
    return ((u64)__float_as_uint(score) << 17) | (u32)(NPB - 1 - idx);
}

// 256-thread top-K boundary pick over smem hist h (bpt bins/thread, bpt*256 bins total).
// Outputs via shared: *sd = boundary bin, *sLab = count strictly above, *sC = count >= bin.
__device__ __forceinline__ void pickTop(u32* h, int bpt, u32* scan, int need,
                                        int* sd, int* sLab, int* sC) {
    int t = threadIdx.x;
    int base = t * bpt;
    u32 ssum = 0;
    for (int q = 0; q < bpt; q++) ssum += h[base + q];
    scan[t] = ssum;
    __syncthreads();
    for (int d = 1; d < 256; d <<= 1) {          // inclusive suffix scan
        u32 v = (t + d < 256) ? scan[t + d] : 0u;
        __syncthreads();
        scan[t] += v;
        __syncthreads();
    }
    u32 above = (t < 255) ? scan[t + 1] : 0u;
    if ((int)scan[t] >= need && (int)above < need) {   // exactly one thread
        u32 cum = above;
        int d;
        for (d = base + bpt - 1;; d--) {
            if ((int)(cum + h[d]) >= need) break;
            cum += h[d];
        }
        *sd = d; *sLab = (int)cum; *sC = (int)(cum + h[d]);
    }
    __syncthreads();
}

// ---------------- K1: ub + per-batch histogram; last block per batch selects T1 ----------------
__global__ void __launch_bounds__(256) ubK(const float* __restrict__ obj,
                                           const float* __restrict__ qual) {
    __shared__ u32 hist[NBIN];
    __shared__ u32 scan[256];
    __shared__ int s_last, s_d, s_L, s_C;
    for (int j = threadIdx.x; j < NBIN; j += 256) hist[j] = 0;
    __syncthreads();

    int bid = blockIdx.x;
    int b = bid / 75;
    int g0 = b * NPB + (bid - b * 75) * 1024 + threadIdx.x * 4;
    float4 o4 = *reinterpret_cast<const float4*>(obj + g0);
    float4 q4 = *reinterpret_cast<const float4*>(qual + g0);
    float u0 = 1.0f / ((1.0f + __expf(-o4.x)) * (1.0f + __expf(-q4.x)));
    float u1 = 1.0f / ((1.0f + __expf(-o4.y)) * (1.0f + __expf(-q4.y)));
    float u2 = 1.0f / ((1.0f + __expf(-o4.z)) * (1.0f + __expf(-q4.z)));
    float u3 = 1.0f / ((1.0f + __expf(-o4.w)) * (1.0f + __expf(-q4.w)));
    *reinterpret_cast<float4*>(g_ub + g0) = make_float4(u0, u1, u2, u3);

    atomicAdd(&hist[__float_as_uint(u0) >> 18], 1u);
    atomicAdd(&hist[__float_as_uint(u1) >> 18], 1u);
    atomicAdd(&hist[__float_as_uint(u2) >> 18], 1u);
    atomicAdd(&hist[__float_as_uint(u3) >> 18], 1u);
    __syncthreads();

    u32* gh = g_ubhist + b * NBIN;
    for (int j = threadIdx.x; j < NBIN; j += 256) {
        u32 v = hist[j];
        if (v) atomicAdd(&gh[j], v);
    }
    __syncthreads();
    if (threadIdx.x == 0) {
        __threadfence();
        s_last = (atomicAdd(&g_tick1[b], 1) == 74) ? 1 : 0;
    }
    __syncthreads();
    if (s_last) {
        for (int j = threadIdx.x; j < NBIN; j += 256) hist[j] = gh[j];
        __syncthreads();
        pickTop(hist, 16, scan, MTARGET, &s_d, &s_L, &s_C);
        if (threadIdx.x == 0) g_T1[b] = (u32)s_d;
    }
}

// ---------------- K2: collect E1 + evaluate + score hist; last block per batch selects T2 -------
__global__ void __launch_bounds__(256) collEvalK(const float* __restrict__ cls) {
    __shared__ int sbuf[1024];
    __shared__ u32 selh[NBIN];
    __shared__ u32 scan[256];
    __shared__ int s_n, s_pos, s_last, s_d, s_L, s_C;
    int tid = threadIdx.x;
    if (tid == 0) { s_n = 0; s_pos = 0; }
    __syncthreads();

    int bid = blockIdx.x;
    int b = bid / 75;
    int i0 = (bid - b * 75) * 1024 + tid * 4;
    u32 T1 = g_T1[b];
    float4 u4 = *reinterpret_cast<const float4*>(g_ub + b * NPB + i0);
    float us[4] = {u4.x, u4.y, u4.z, u4.w};
#pragma unroll
    for (int j = 0; j < 4; j++) {
        if ((__float_as_uint(us[j]) >> 18) >= T1) {
            int p = atomicAdd(&s_n, 1);          // shared atomic: cheap
            sbuf[p] = i0 + j;
        }
    }
    __syncthreads();
    if (tid == 0 && s_n) s_pos = atomicAdd(&g_cnt1[b], s_n);   // ONE global atomic per block
    __syncthreads();

    int n = s_n, pos = s_pos;
    int lane = tid & 31, warp = tid >> 5;
    for (int j = warp; j < n; j += 8) {
        u64 key = evalCand(cls, b, sbuf[j], lane);
        if (lane == 0) {
            g_keys[(size_t)b * NPB + pos + j] = key;
            atomicAdd(&g_schist[b * NBIN + (u32)(key >> 35)], 1u);
        }
    }
    __syncthreads();
    if (tid == 0) {
        __threadfence();
        s_last = (atomicAdd(&g_tick2[b], 1) == 74) ? 1 : 0;
    }
    __syncthreads();
    if (s_last) {
        const u32* gh = g_schist + b * NBIN;
        for (int j = tid; j < NBIN; j += 256) selh[j] = gh[j];
        __syncthreads();
        pickTop(selh, 16, scan, TOPKK, &s_d, &s_L, &s_C);
        if (tid == 0) g_T2[b] = (u32)s_d;
    }
}

// ---------------- K3: blocks 8..607 = E2 collect+eval; blocks 0..7 = finalize batch ------------
__global__ void __launch_bounds__(256) finE2K(const float* __restrict__ cls,
                                              const float* __restrict__ box,
                                              const float* __restrict__ anch,
                                              float* __restrict__ out) {
    __shared__ u32 shh[NBIN];        // 16 KB (finalize hist; unused by E2 blocks)
    __shared__ int sbuf[1024];       // 4 KB  (E2 tile buffer / finalize sub-hist)
    __shared__ u32 scan[256];        // 1 KB
    __shared__ u64 cand[CANDCAP];    // 1.5 KB
    __shared__ int s_n, s_pos, s_d, s_L, s_C, s_cnt;

    int tid = threadIdx.x, lane = tid & 31, warp = tid >> 5;

    if (blockIdx.x >= BATCH) {
        // ---------------- E2 tile: ub bin in [T2, T1) ----------------
        int t = blockIdx.x - BATCH;
        int b = t / 75;
        u32 T1 = g_T1[b], T2 = g_T2[b];
        if (T2 < T1) {
            if (tid == 0) s_n = 0;
            __syncthreads();
            int i0 = (t - b * 75) * 1024 + tid * 4;
            float4 u4 = *reinterpret_cast<const float4*>(g_ub + b * NPB + i0);
            float us[4] = {u4.x, u4.y, u4.z, u4.w};
#pragma unroll
            for (int j = 0; j < 4; j++) {
                u32 bin = __float_as_uint(us[j]) >> 18;
                if (bin >= T2 && bin < T1) {
                    int p = atomicAdd(&s_n, 1);
                    sbuf[p] = i0 + j;
                }
            }
            __syncthreads();
            if (tid == 0 && s_n) s_pos = g_cnt1[b] + atomicAdd(&g_cnt2[b], s_n);
            __syncthreads();
            int n = s_n, pos = s_pos;
            for (int j = warp; j < n; j += 8) {
                u64 key = evalCand(cls, b, sbuf[j], lane);
                if (lane == 0) g_keys[(size_t)b * NPB + pos + j] = key;
            }
            __syncthreads();
        }
        if (tid == 0) {
            __threadfence();
            atomicAdd(&g_tick3[b], 1);
        }
        return;
    }

    // ---------------- finalize batch b: exact top-100 over all M keys ----------------
    int b = blockIdx.x;
    if (tid == 0) {
        volatile int* vt = &g_tick3[b];
        while (*vt < 75) __nanosleep(64);
    }
    __syncthreads();
    __threadfence();

    int M = g_cnt1[b] + g_cnt2[b];
    const u64* keys = g_keys + (size_t)b * NPB;

    // level 0: 4096-bin histogram of key>>35 (score bits >> 18)
    for (int j = tid; j < NBIN; j += 256) shh[j] = 0;
    __syncthreads();
    for (int j = tid; j < M; j += 256)
        atomicAdd(&shh[(u32)(keys[j] >> 35)], 1u);
    __syncthreads();
    pickTop(shh, 16, scan, TOPKK, &s_d, &s_L, &s_C);
    u64 P = (u64)(u32)s_d;
    int s = 35, L = s_L, C = s_C;
    __syncthreads();

    // 10-bit refinement levels (25, 15, 5); invariant L < 100 at every level.
    // At s=5 a bucket holds <=32 keys (low idx bits), so C <= 131 <= CANDCAP guaranteed.
    u32* subh = reinterpret_cast<u32*>(sbuf);
    while (C > CANDCAP && s > 5) {
        int s2 = s - 10;
        for (int j = tid; j < 1024; j += 256) subh[j] = 0;
        __syncthreads();
        for (int j = tid; j < M; j += 256) {
            u64 k = keys[j];
            if ((k >> s) == P) atomicAdd(&subh[(u32)(k >> s2) & 1023], 1u);
        }
        __syncthreads();
        pickTop(subh, 4, scan, TOPKK - L, &s_d, &s_L, &s_C);
        int Lsub = s_L, Csub = s_C;
        __syncthreads();
        P = (P << 10) | (u32)s_d;
        s = s2;
        C = L + Csub;
        L = L + Lsub;
    }

    // collect candidates >= threshold (C <= CANDCAP guaranteed)
    if (tid == 0) s_cnt = 0;
    __syncthreads();
    for (int j = tid; j < M; j += 256) {
        u64 k = keys[j];
        if ((k >> s) >= P) {
            int pos = atomicAdd(&s_cnt, 1);
            if (pos < CANDCAP) cand[pos] = k;
        }
    }
    __syncthreads();
    int Cn = min(s_cnt, CANDCAP);

    // rank by counting (keys distinct -> exact permutation), decode inline
    for (int i = tid; i < Cn; i += 256) {
        u64 k = cand[i];
        int r = 0;
        for (int j = 0; j < Cn; j++) r += (cand[j] > k);
        if (r < TOPKK) {
            u32 sb = (u32)(k >> 17);
            int idx = NPB - 1 - (int)(k & 0x1FFFFu);
            int a = idx / HW;
            int pix = idx - a * HW;
            int y = pix / WW;
            int x = pix - y * WW;
            int c = (int)g_cls[b * NPB + idx];
            const float* bp = box + (size_t)(b * NA + a) * 4 * HW + pix;
            float tx = bp[0];
            float ty = bp[(size_t)HW];
            float tw = bp[2 * (size_t)HW];
            float th = bp[3 * (size_t)HW];
            float aw = anch[a * 2 + 0];
            float ah = anch[a * 2 + 1];
            float cx = (fsig(tx) + (float)x) / (float)WW;
            float cy = (fsig(ty) + (float)y) / (float)HH;
            // faithful softplus: relu(x) + log1p(exp(-|x|))
            float spw = fmaxf(tw, 0.0f) + log1pf(__expf(-fabsf(tw)));
            float sph = fmaxf(th, 0.0f) + log1pf(__expf(-fabsf(th)));
            float* o = out + ((size_t)b * TOPKK + r) * 6;
            o[0] = __uint_as_float(sb);
            o[1] = (float)c;
            o[2] = cx;
            o[3] = cy;
            o[4] = aw * spw;
            o[5] = ah * sph;
        }
    }

    // reset batch-b scratch for the next replay (device globals start zeroed on load)
    __syncthreads();
    for (int j = tid; j < NBIN; j += 256) {
        g_ubhist[b * NBIN + j] = 0;
        g_schist[b * NBIN + j] = 0;
    }
    if (tid == 0) {
        g_cnt1[b] = 0; g_cnt2[b] = 0;
        g_tick1[b] = 0; g_tick2[b] = 0; g_tick3[b] = 0;
    }
}

// ---------------- launch ----------------
extern "C" void kernel_launch(void* const* d_in, const int* in_sizes, int n_in,
                              void* d_out, int out_size) {
    const float* box  = (const float*)d_in[0];
    const float* obj  = (const float*)d_in[1];
    const float* qual = (const float*)d_in[2];
    const float* cls  = (const float*)d_in[3];
    const float* anch = (const float*)d_in[4];
    int seen = 0;
    for (int i = 0; i < n_in; i++) {
        int s = in_sizes[i];
        if (s == BATCH * NA * 4 * HW) box = (const float*)d_in[i];
        else if (s == BATCH * NA * NC * HW) cls = (const float*)d_in[i];
        else if (s == NA * 2) anch = (const float*)d_in[i];
        else if (s == BATCH * NA * HW) {
            if (seen == 0) obj = (const float*)d_in[i];
            else qual = (const float*)d_in[i];
            seen++;
        }
    }
    float* out = (float*)d_out;

    ubK<<<600, 256>>>(obj, qual);
    collEvalK<<<600, 256>>>(cls);
    finE2K<<<608, 256>>>(cls, box, anch, out);
}